// round 9
// baseline (speedup 1.0000x reference)
#include <cuda_runtime.h>
#include <cuda_fp16.h>
#include <math.h>
#include <stdint.h>

typedef __half fp16;

#define Dc   1024
#define Ec   8
#define Fc   4096
#define NTOK 8192
#define NSLOT (NTOK * 2)
#define PADR 128
#define MAX_TILES 136
#define BM 128
#define BN 256
#define BK 32
#define NTHR 512

// smem stage: A 128 rows + B 256 rows, each row 80B (32 fp16 = 64B data + 16B pad)
#define ROWB 80
#define ST_A 0
#define ST_B (128 * ROWB)
#define STAGE ((128 + 256) * ROWB)   // 30720 B
#define NSTG 4
#define SMEM_DYN (NSTG * STAGE)      // 122880 B

// ---------------- scratch (device globals) ---------------------------------
__device__ __align__(1024) fp16  g_xg [(size_t)(NSLOT + PADR) * Dc];
__device__ __align__(1024) fp16  g_h  [(size_t)(NSLOT + PADR) * Fc];
__device__ __align__(1024) float g_y  [(size_t)NSLOT * Dc];          // per-slot GEMM2 output
__device__ __align__(1024) fp16  g_W1t[(size_t)Ec * Fc * Dc];        // [e][f][d]
__device__ __align__(1024) fp16  g_W2t[(size_t)Ec * Dc * Fc];        // [e][d][f]
__device__ int   g_perm[NSLOT];
__device__ int   g_tok_slot[NTOK * 2];   // token -> its 2 slots
__device__ int   g_tok_e[NTOK * 2];
__device__ float g_tok_w[NTOK * 2];
__device__ int   g_count[Ec];
__device__ int   g_cursor[Ec];
__device__ int   g_tile_base[MAX_TILES];
__device__ int   g_tile_expert[MAX_TILES];
__device__ int   g_tile_rows[MAX_TILES];
__device__ int   g_ntiles;

// ---------------- helpers ----------------------------------------------------
__device__ __forceinline__ uint32_t smem_u32(const void* p) {
    uint32_t a;
    asm("{ .reg .u64 t; cvta.to.shared.u64 t, %1; cvt.u32.u64 %0, t; }" : "=r"(a) : "l"(p));
    return a;
}
__device__ __forceinline__ void cp16(uint32_t s, const void* g) {
    asm volatile("cp.async.cg.shared.global [%0], [%1], 16;" :: "r"(s), "l"(g));
}
__device__ __forceinline__ void cp_commit() { asm volatile("cp.async.commit_group;" ::: "memory"); }
#define CP_WAIT(n) asm volatile("cp.async.wait_group %0;" :: "n"(n) : "memory")

__device__ __forceinline__ void ldmx4(uint32_t addr, uint32_t r[4]) {
    asm volatile("ldmatrix.sync.aligned.m8n8.x4.shared.b16 {%0,%1,%2,%3}, [%4];"
        : "=r"(r[0]), "=r"(r[1]), "=r"(r[2]), "=r"(r[3]) : "r"(addr));
}
__device__ __forceinline__ void mma16816(float c[4], const uint32_t a[4], const uint32_t* b) {
    asm volatile("mma.sync.aligned.m16n8k16.row.col.f32.f16.f16.f32 "
        "{%0,%1,%2,%3}, {%4,%5,%6,%7}, {%8,%9}, {%0,%1,%2,%3};"
        : "+f"(c[0]), "+f"(c[1]), "+f"(c[2]), "+f"(c[3])
        : "r"(a[0]), "r"(a[1]), "r"(a[2]), "r"(a[3]), "r"(b[0]), "r"(b[1]));
}
__device__ __forceinline__ float gelu_exact(float v) {
    return 0.5f * v * (1.0f + erff(v * 0.70710678118654752f));
}
__device__ __forceinline__ uint32_t pack2(fp16 a, fp16 b) {
    return (uint32_t)__half_as_ushort(a) | ((uint32_t)__half_as_ushort(b) << 16);
}

// ---------------- gate (fp32, exact routing) ---------------------------------
__global__ void k_gate(const float* __restrict__ x, const float* __restrict__ Wg,
                       const float* __restrict__ bg) {
    int gtid = blockIdx.x * blockDim.x + threadIdx.x;
    int tok = gtid >> 5, lane = gtid & 31;
    if (tok >= NTOK) return;
    const float* xr = x + (size_t)tok * Dc;
    float acc[Ec];
#pragma unroll
    for (int e = 0; e < Ec; e++) acc[e] = 0.0f;
    for (int d = lane; d < Dc; d += 32) {
        float xv = xr[d];
        const float4* wr = (const float4*)(Wg + (size_t)d * Ec);
        float4 w0 = wr[0], w1 = wr[1];
        acc[0] += xv * w0.x; acc[1] += xv * w0.y; acc[2] += xv * w0.z; acc[3] += xv * w0.w;
        acc[4] += xv * w1.x; acc[5] += xv * w1.y; acc[6] += xv * w1.z; acc[7] += xv * w1.w;
    }
#pragma unroll
    for (int e = 0; e < Ec; e++)
#pragma unroll
        for (int off = 16; off > 0; off >>= 1)
            acc[e] += __shfl_down_sync(0xFFFFFFFFu, acc[e], off);
    if (lane == 0) {
        float v[Ec];
#pragma unroll
        for (int e = 0; e < Ec; e++) v[e] = acc[e] + bg[e];
        int b0 = 0;
#pragma unroll
        for (int e = 1; e < Ec; e++) if (v[e] > v[b0]) b0 = e;
        int b1 = -1; float s = -1e30f;
#pragma unroll
        for (int e = 0; e < Ec; e++) { if (e == b0) continue; if (v[e] > s) { s = v[e]; b1 = e; } }
        float ed = expf(s - v[b0]);
        float p0 = 1.0f / (1.0f + ed);
        float p1 = ed * p0;
        g_tok_e[tok * 2 + 0] = b0; g_tok_e[tok * 2 + 1] = b1;
        g_tok_w[tok * 2 + 0] = p0; g_tok_w[tok * 2 + 1] = p1;
        atomicAdd(&g_count[b0], 1);
        atomicAdd(&g_count[b1], 1);
    }
}

// ---------------- scatter (prefix computed per-thread) ------------------------
__global__ void k_scatter() {
    int t = blockIdx.x * blockDim.x + threadIdx.x;
    if (t >= NTOK) return;
    int off[Ec];
    {
        int run = 0;
#pragma unroll
        for (int e = 0; e < Ec; e++) { off[e] = run; run += g_count[e]; }
    }
#pragma unroll
    for (int k = 0; k < 2; k++) {
        int e = g_tok_e[t * 2 + k];
        int pos = off[e] + atomicAdd(&g_cursor[e], 1);
        g_perm[pos] = t;
        g_tok_slot[t * 2 + k] = pos;
    }
}

// ---------------- gather x rows -> fp16 (+ tile list build in block 0) -------
__global__ void k_gather(const float* __restrict__ x) {
    int s = blockIdx.x;
    int tid = threadIdx.x;
    if (s == 0 && tid == 0) {
        int off = 0, nt = 0;
        for (int e = 0; e < Ec; e++) {
            int c = g_count[e];
            for (int q = 0; q < c; q += BM) {
                g_tile_base[nt] = off + q; g_tile_expert[nt] = e;
                g_tile_rows[nt] = min(BM, c - q); nt++;
            }
            off += c;
        }
        g_ntiles = nt;
    }
    if (s < NSLOT) {
        const float* src = x + (size_t)g_perm[s] * Dc;
        for (int d = tid * 2; d < Dc; d += 512) {
            float2 v = *(const float2*)(src + d);
            *(uint32_t*)(g_xg + (size_t)s * Dc + d) =
                pack2(__float2half_rn(v.x), __float2half_rn(v.y));
        }
    } else {
        for (int d = tid * 2; d < Dc; d += 512)
            *(uint32_t*)(g_xg + (size_t)s * Dc + d) = 0u;
    }
}

// ---------------- weight transpose: in [e][R][C] fp32 -> out [e][C][R] fp16 --
__global__ void k_tsplit(const float* __restrict__ in, int which, int R, int C,
                         int zero_flag) {
    fp16* o = which ? g_W2t : g_W1t;
    __shared__ float t[32][33];
    int e = blockIdx.z;
    int r0 = blockIdx.y * 32, c0 = blockIdx.x * 32;
    int tx = threadIdx.x, ty = threadIdx.y;
    if (zero_flag && blockIdx.x == 0 && blockIdx.y == 0 && blockIdx.z == 0 &&
        ty == 0 && tx < Ec) {
        g_count[tx] = 0;
        g_cursor[tx] = 0;
    }
    const float* base = in + (size_t)e * R * C;
#pragma unroll
    for (int i = 0; i < 4; i++)
        t[ty + 8 * i][tx] = base[(size_t)(r0 + ty + 8 * i) * C + c0 + tx];
    __syncthreads();
    size_t ob = (size_t)e * C * R;
#pragma unroll
    for (int i = 0; i < 4; i++) {
        float v = t[tx][ty + 8 * i];
        o[ob + (size_t)(c0 + ty + 8 * i) * R + r0 + tx] = __float2half_rn(v);
    }
}

// ---------------- GEMM core ---------------------------------------------------
// CTA 128x256x32, 512 threads: 16 warps in 4(M) x 4(N) grid, warp tile 32x64.
// 1 CTA/SM (122.9KB smem), 16 warps/SM.
__device__ __forceinline__ void load_stage(uint32_t sb,
        const fp16* __restrict__ A, const fp16* __restrict__ B,
        int ldk, int k0, int tid) {
    // A: 128 rows x 32 cols = 512 x 16B ops -> 1 per thread
    {
        int row = tid >> 2, cpos = tid & 3;
        cp16(sb + ST_A + (uint32_t)row * ROWB + cpos * 16,
             A + (size_t)row * ldk + k0 + cpos * 8);
    }
    // B: 256 rows x 32 cols = 1024 x 16B ops -> 2 per thread
#pragma unroll
    for (int i = 0; i < 2; i++) {
        int idx = tid * 2 + i;
        int row = idx >> 2, cpos = idx & 3;
        cp16(sb + ST_B + (uint32_t)row * ROWB + cpos * 16,
             B + (size_t)row * ldk + k0 + cpos * 8);
    }
}

__device__ __forceinline__ void gemm_core(uint32_t sm0,
        const fp16* __restrict__ A, const fp16* __restrict__ B,
        int ldk, int NC, int tid, float (&acc)[2][8][4]) {
    const int lane = tid & 31, wid = tid >> 5;
    const int wm = (wid & 3) * 32, wn = (wid >> 2) * 64;

    const uint32_t a_off = (uint32_t)(wm + (lane & 15)) * ROWB + ((lane & 16) ? 16u : 0u);
    const uint32_t b_off = (uint32_t)(wn + (lane & 7) + ((lane & 16) >> 1)) * ROWB
                           + ((lane & 8) ? 16u : 0u);

#pragma unroll
    for (int mt = 0; mt < 2; mt++)
#pragma unroll
        for (int nt = 0; nt < 8; nt++)
#pragma unroll
            for (int q = 0; q < 4; q++) acc[mt][nt][q] = 0.0f;

    // prologue: 3 stages in flight
#pragma unroll
    for (int s = 0; s < 3; s++) {
        load_stage(sm0 + (uint32_t)s * STAGE, A, B, ldk, s * BK, tid);
        cp_commit();
    }

    for (int k = 0; k < NC; k++) {
        int rem = NC - 1 - k;
        if (rem >= 2)      { CP_WAIT(2); }
        else if (rem == 1) { CP_WAIT(1); }
        else               { CP_WAIT(0); }
        __syncthreads();
        if (k + 3 < NC) {
            load_stage(sm0 + (uint32_t)((k + 3) & (NSTG - 1)) * STAGE, A, B,
                       ldk, (k + 3) * BK, tid);
            cp_commit();
        }
        uint32_t sb = sm0 + (uint32_t)(k & (NSTG - 1)) * STAGE;
#pragma unroll
        for (int kk = 0; kk < 2; kk++) {
            const uint32_t kb = kk * 32;
            // batch all LDSMs of this k16 step before the MMAs
            uint32_t ah[2][4], bh[4][4];
#pragma unroll
            for (int mt = 0; mt < 2; mt++)
                ldmx4(sb + ST_A + a_off + mt * 16 * ROWB + kb, ah[mt]);
#pragma unroll
            for (int p = 0; p < 4; p++)
                ldmx4(sb + ST_B + b_off + p * 16 * ROWB + kb, bh[p]);
#pragma unroll
            for (int p = 0; p < 4; p++)
#pragma unroll
                for (int q = 0; q < 2; q++)
#pragma unroll
                    for (int mt = 0; mt < 2; mt++)
                        mma16816(acc[mt][p * 2 + q], ah[mt], &bh[p][q * 2]);
        }
        __syncthreads();
    }
}

// ---------------- GEMM1: h = fp16(gelu(xg @ W1t^T + b1)) ----------------------
__global__ void __launch_bounds__(NTHR, 1)
k_mma1(const float* __restrict__ b1) {
    int t = blockIdx.y;
    if (t >= g_ntiles) return;
    const int n0 = blockIdx.x * BN;
    const int base = g_tile_base[t], e = g_tile_expert[t], rows = g_tile_rows[t];

    extern __shared__ char dsm[];
    uint32_t sm0 = smem_u32(dsm);
    int tid = threadIdx.x;

    float acc[2][8][4];
    gemm_core(sm0, g_xg + (size_t)base * Dc,
              g_W1t + ((size_t)e * Fc + n0) * Dc, Dc, Dc / BK, tid, acc);

    const int lane = tid & 31, wid = tid >> 5;
    const int wm = (wid & 3) * 32, wn = (wid >> 2) * 64;
    const int rb = wm + (lane >> 2);
    const int cb = wn + (lane & 3) * 2;
    const float* b1e = b1 + (size_t)e * Fc + n0;
    float bv[8][2];
#pragma unroll
    for (int nt = 0; nt < 8; nt++) {
        bv[nt][0] = b1e[cb + nt * 8];
        bv[nt][1] = b1e[cb + nt * 8 + 1];
    }
#pragma unroll
    for (int mt = 0; mt < 2; mt++)
#pragma unroll
        for (int half = 0; half < 2; half++) {
            int r = rb + mt * 16 + half * 8;
            if (r >= rows) continue;
            size_t ro = (size_t)(base + r) * Fc + n0;
#pragma unroll
            for (int nt = 0; nt < 8; nt++) {
                float v0 = gelu_exact(acc[mt][nt][half * 2 + 0] + bv[nt][0]);
                float v1 = gelu_exact(acc[mt][nt][half * 2 + 1] + bv[nt][1]);
                *(uint32_t*)(g_h + ro + cb + nt * 8) =
                    pack2(__float2half_rn(v0), __float2half_rn(v1));
            }
        }
}

// ---------------- GEMM2: y[slot] = h @ W2t^T + b2 (plain stores) --------------
__global__ void __launch_bounds__(NTHR, 1)
k_mma2(const float* __restrict__ b2) {
    int t = blockIdx.y;
    if (t >= g_ntiles) return;
    const int n0 = blockIdx.x * BN;
    const int base = g_tile_base[t], e = g_tile_expert[t], rows = g_tile_rows[t];

    extern __shared__ char dsm[];
    uint32_t sm0 = smem_u32(dsm);
    int tid = threadIdx.x;

    float acc[2][8][4];
    gemm_core(sm0, g_h + (size_t)base * Fc,
              g_W2t + ((size_t)e * Dc + n0) * Fc, Fc, Fc / BK, tid, acc);

    const int lane = tid & 31, wid = tid >> 5;
    const int wm = (wid & 3) * 32, wn = (wid >> 2) * 64;
    const int rb = wm + (lane >> 2);
    const int cb = wn + (lane & 3) * 2;
    const float* b2e = b2 + (size_t)e * Dc + n0;
    float bv[8][2];
#pragma unroll
    for (int nt = 0; nt < 8; nt++) {
        bv[nt][0] = b2e[cb + nt * 8];
        bv[nt][1] = b2e[cb + nt * 8 + 1];
    }
#pragma unroll
    for (int mt = 0; mt < 2; mt++)
#pragma unroll
        for (int half = 0; half < 2; half++) {
            int r = rb + mt * 16 + half * 8;
            if (r >= rows) continue;
            float* yrow = g_y + (size_t)(base + r) * Dc + n0;
#pragma unroll
            for (int nt = 0; nt < 8; nt++) {
                int c = cb + nt * 8;
                float2 v;
                v.x = acc[mt][nt][half * 2 + 0] + bv[nt][0];
                v.y = acc[mt][nt][half * 2 + 1] + bv[nt][1];
                *(float2*)(yrow + c) = v;
            }
        }
}

// ---------------- combine: out[t] = w0*y[s0] + w1*y[s1] -----------------------
__global__ void k_combine(float* __restrict__ out) {
    int t = blockIdx.x;
    int tid = threadIdx.x;
    int s0 = g_tok_slot[t * 2 + 0], s1 = g_tok_slot[t * 2 + 1];
    float w0 = g_tok_w[t * 2 + 0],  w1 = g_tok_w[t * 2 + 1];
    const float4* y0 = (const float4*)(g_y + (size_t)s0 * Dc);
    const float4* y1 = (const float4*)(g_y + (size_t)s1 * Dc);
    float4* o = (float4*)(out + (size_t)t * Dc);
    float4 a = y0[tid], b = y1[tid];
    float4 r;
    r.x = w0 * a.x + w1 * b.x;
    r.y = w0 * a.y + w1 * b.y;
    r.z = w0 * a.z + w1 * b.z;
    r.w = w0 * a.w + w1 * b.w;
    o[tid] = r;
}

// ---------------- launch -------------------------------------------------------
extern "C" void kernel_launch(void* const* d_in, const int* in_sizes, int n_in,
                              void* d_out, int out_size) {
    const float* x  = (const float*)d_in[0];
    const float* Wg = (const float*)d_in[1];
    const float* bg = (const float*)d_in[2];
    const float* W1 = (const float*)d_in[3];
    const float* b1 = (const float*)d_in[4];
    const float* W2 = (const float*)d_in[5];
    const float* b2 = (const float*)d_in[6];
    float* out = (float*)d_out;

    static int configured = 0;
    if (!configured) {
        cudaFuncSetAttribute(k_mma1, cudaFuncAttributeMaxDynamicSharedMemorySize, SMEM_DYN);
        cudaFuncSetAttribute(k_mma2, cudaFuncAttributeMaxDynamicSharedMemorySize, SMEM_DYN);
        configured = 1;
    }

    k_tsplit<<<dim3(Fc / 32, Dc / 32, Ec), dim3(32, 8)>>>(W1, 0, Dc, Fc, 1);  // +zero counters
    k_tsplit<<<dim3(Dc / 32, Fc / 32, Ec), dim3(32, 8)>>>(W2, 1, Fc, Dc, 0);
    k_gate<<<NTOK / 8, 256>>>(x, Wg, bg);
    k_scatter<<<NTOK / 256, 256>>>();
    k_gather<<<NSLOT + PADR, 256>>>(x);
    k_mma1<<<dim3(Fc / BN, MAX_TILES), NTHR, SMEM_DYN>>>(b1);
    k_mma2<<<dim3(Dc / BN, MAX_TILES), NTHR, SMEM_DYN>>>(b2);
    k_combine<<<NTOK, 256>>>(out);
}

// round 10
// speedup vs baseline: 1.1159x; 1.1159x over previous
#include <cuda_runtime.h>
#include <cuda_fp16.h>
#include <math.h>
#include <stdint.h>

typedef __half fp16;

#define Dc   1024
#define Ec   8
#define Fc   4096
#define NTOK 8192
#define NSLOT (NTOK * 2)
#define PADR 128
#define MAX_TILES 136
#define BM 128
#define BN 128
#define BK 32

// smem stage: 2 tiles (A, B), 128 rows x 80B (32 fp16 = 64B data + 16B pad)
#define ROWB 80
#define ST_A 0
#define ST_B (128 * ROWB)
#define STAGE (2 * 128 * ROWB)      // 20480 B
#define NSTG 4
#define SMEM_DYN (NSTG * STAGE)     // 81920 B

// ---------------- scratch (device globals) ---------------------------------
__device__ __align__(1024) fp16  g_xg [(size_t)(NSLOT + PADR) * Dc];
__device__ __align__(1024) fp16  g_h  [(size_t)(NSLOT + PADR) * Fc];
__device__ __align__(1024) float g_y  [(size_t)NSLOT * Dc];          // per-slot GEMM2 output
__device__ __align__(1024) fp16  g_W1t[(size_t)Ec * Fc * Dc];        // [e][f][d]
__device__ __align__(1024) fp16  g_W2t[(size_t)Ec * Dc * Fc];        // [e][d][f]
__device__ int   g_perm[NSLOT];
__device__ int   g_tok_slot[NTOK * 2];   // token -> its 2 slots
__device__ int   g_tok_e[NTOK * 2];
__device__ float g_tok_w[NTOK * 2];
__device__ int   g_count[Ec];
__device__ int   g_cursor[Ec];
__device__ int   g_tile_base[MAX_TILES];
__device__ int   g_tile_expert[MAX_TILES];
__device__ int   g_tile_rows[MAX_TILES];
__device__ int   g_ntiles;

// ---------------- helpers ----------------------------------------------------
__device__ __forceinline__ uint32_t smem_u32(const void* p) {
    uint32_t a;
    asm("{ .reg .u64 t; cvta.to.shared.u64 t, %1; cvt.u32.u64 %0, t; }" : "=r"(a) : "l"(p));
    return a;
}
__device__ __forceinline__ void cp16(uint32_t s, const void* g) {
    asm volatile("cp.async.cg.shared.global [%0], [%1], 16;" :: "r"(s), "l"(g));
}
__device__ __forceinline__ void cp_commit() { asm volatile("cp.async.commit_group;" ::: "memory"); }
#define CP_WAIT(n) asm volatile("cp.async.wait_group %0;" :: "n"(n) : "memory")

__device__ __forceinline__ void ldmx4(uint32_t addr, uint32_t r[4]) {
    asm volatile("ldmatrix.sync.aligned.m8n8.x4.shared.b16 {%0,%1,%2,%3}, [%4];"
        : "=r"(r[0]), "=r"(r[1]), "=r"(r[2]), "=r"(r[3]) : "r"(addr));
}
__device__ __forceinline__ void mma16816(float c[4], const uint32_t a[4], const uint32_t* b) {
    asm volatile("mma.sync.aligned.m16n8k16.row.col.f32.f16.f16.f32 "
        "{%0,%1,%2,%3}, {%4,%5,%6,%7}, {%8,%9}, {%0,%1,%2,%3};"
        : "+f"(c[0]), "+f"(c[1]), "+f"(c[2]), "+f"(c[3])
        : "r"(a[0]), "r"(a[1]), "r"(a[2]), "r"(a[3]), "r"(b[0]), "r"(b[1]));
}
__device__ __forceinline__ float gelu_exact(float v) {
    return 0.5f * v * (1.0f + erff(v * 0.70710678118654752f));
}
__device__ __forceinline__ uint32_t pack2(fp16 a, fp16 b) {
    return (uint32_t)__half_as_ushort(a) | ((uint32_t)__half_as_ushort(b) << 16);
}

// ---------------- init (counters only) ----------------------------------------
__global__ void k_init() {
    int i = threadIdx.x;
    if (i < Ec) g_count[i] = 0;
}

// ---------------- gate (fp32, exact routing) ---------------------------------
__global__ void k_gate(const float* __restrict__ x, const float* __restrict__ Wg,
                       const float* __restrict__ bg) {
    int gtid = blockIdx.x * blockDim.x + threadIdx.x;
    int tok = gtid >> 5, lane = gtid & 31;
    if (tok >= NTOK) return;
    const float* xr = x + (size_t)tok * Dc;
    float acc[Ec];
#pragma unroll
    for (int e = 0; e < Ec; e++) acc[e] = 0.0f;
    for (int d = lane; d < Dc; d += 32) {
        float xv = xr[d];
        const float4* wr = (const float4*)(Wg + (size_t)d * Ec);
        float4 w0 = wr[0], w1 = wr[1];
        acc[0] += xv * w0.x; acc[1] += xv * w0.y; acc[2] += xv * w0.z; acc[3] += xv * w0.w;
        acc[4] += xv * w1.x; acc[5] += xv * w1.y; acc[6] += xv * w1.z; acc[7] += xv * w1.w;
    }
#pragma unroll
    for (int e = 0; e < Ec; e++)
#pragma unroll
        for (int off = 16; off > 0; off >>= 1)
            acc[e] += __shfl_down_sync(0xFFFFFFFFu, acc[e], off);
    if (lane == 0) {
        float v[Ec];
#pragma unroll
        for (int e = 0; e < Ec; e++) v[e] = acc[e] + bg[e];
        int b0 = 0;
#pragma unroll
        for (int e = 1; e < Ec; e++) if (v[e] > v[b0]) b0 = e;
        int b1 = -1; float s = -1e30f;
#pragma unroll
        for (int e = 0; e < Ec; e++) { if (e == b0) continue; if (v[e] > s) { s = v[e]; b1 = e; } }
        float ed = expf(s - v[b0]);
        float p0 = 1.0f / (1.0f + ed);
        float p1 = ed * p0;
        g_tok_e[tok * 2 + 0] = b0; g_tok_e[tok * 2 + 1] = b1;
        g_tok_w[tok * 2 + 0] = p0; g_tok_w[tok * 2 + 1] = p1;
        atomicAdd(&g_count[b0], 1);
        atomicAdd(&g_count[b1], 1);
    }
}

__global__ void k_setup() {
    int off = 0, nt = 0;
    for (int e = 0; e < Ec; e++) {
        int c = g_count[e];
        g_cursor[e] = off;
        for (int s = 0; s < c; s += BM) {
            g_tile_base[nt] = off + s; g_tile_expert[nt] = e;
            g_tile_rows[nt] = min(BM, c - s); nt++;
        }
        off += c;
    }
    g_ntiles = nt;
}

__global__ void k_scatter() {
    int t = blockIdx.x * blockDim.x + threadIdx.x;
    if (t >= NTOK) return;
#pragma unroll
    for (int k = 0; k < 2; k++) {
        int e = g_tok_e[t * 2 + k];
        int pos = atomicAdd(&g_cursor[e], 1);
        g_perm[pos] = t;
        g_tok_slot[t * 2 + k] = pos;
    }
}

// ---------------- gather x rows -> fp16 --------------------------------------
__global__ void k_gather(const float* __restrict__ x) {
    int s = blockIdx.x;
    int tid = threadIdx.x;
    if (s < NSLOT) {
        const float* src = x + (size_t)g_perm[s] * Dc;
        for (int d = tid * 2; d < Dc; d += 512) {
            float2 v = *(const float2*)(src + d);
            *(uint32_t*)(g_xg + (size_t)s * Dc + d) =
                pack2(__float2half_rn(v.x), __float2half_rn(v.y));
        }
    } else {
        for (int d = tid * 2; d < Dc; d += 512)
            *(uint32_t*)(g_xg + (size_t)s * Dc + d) = 0u;
    }
}

// ---------------- weight transpose: in [e][R][C] fp32 -> out [e][C][R] fp16 --
__global__ void k_tsplit(const float* __restrict__ in, int which, int R, int C) {
    fp16* o = which ? g_W2t : g_W1t;
    __shared__ float t[32][33];
    int e = blockIdx.z;
    int r0 = blockIdx.y * 32, c0 = blockIdx.x * 32;
    int tx = threadIdx.x, ty = threadIdx.y;
    const float* base = in + (size_t)e * R * C;
#pragma unroll
    for (int i = 0; i < 4; i++)
        t[ty + 8 * i][tx] = base[(size_t)(r0 + ty + 8 * i) * C + c0 + tx];
    __syncthreads();
    size_t ob = (size_t)e * C * R;
#pragma unroll
    for (int i = 0; i < 4; i++) {
        float v = t[tx][ty + 8 * i];
        o[ob + (size_t)(c0 + ty + 8 * i) * R + r0 + tx] = __float2half_rn(v);
    }
}

// ---------------- GEMM core (R7 exact: proven best) ---------------------------
// CTA 128x128x32, 8 warps in 4(M) x 2(N) grid, warp tile 32x64. 2 CTAs/SM.
__device__ __forceinline__ void load_stage(uint32_t sb,
        const fp16* __restrict__ A, const fp16* __restrict__ B,
        int ldk, int k0, int tid) {
#pragma unroll
    for (int i = 0; i < 2; i++) {
        int idx = tid * 2 + i;
        int row = idx >> 2, cpos = idx & 3;
        uint32_t so = (uint32_t)row * ROWB + cpos * 16;
        size_t go = (size_t)row * ldk + k0 + cpos * 8;
        cp16(sb + ST_A + so, A + go);
        cp16(sb + ST_B + so, B + go);
    }
}

__device__ __forceinline__ void gemm_core(uint32_t sm0,
        const fp16* __restrict__ A, const fp16* __restrict__ B,
        int ldk, int NC, int tid, float (&acc)[2][8][4]) {
    const int lane = tid & 31, wid = tid >> 5;
    const int wm = (wid & 3) * 32, wn = (wid >> 2) * 64;

    const uint32_t a_off = (uint32_t)(wm + (lane & 15)) * ROWB + ((lane & 16) ? 16u : 0u);
    const uint32_t b_off = (uint32_t)(wn + (lane & 7) + ((lane & 16) >> 1)) * ROWB
                           + ((lane & 8) ? 16u : 0u);

#pragma unroll
    for (int mt = 0; mt < 2; mt++)
#pragma unroll
        for (int nt = 0; nt < 8; nt++)
#pragma unroll
            for (int q = 0; q < 4; q++) acc[mt][nt][q] = 0.0f;

    // prologue: 3 stages in flight
#pragma unroll
    for (int s = 0; s < 3; s++) {
        load_stage(sm0 + (uint32_t)s * STAGE, A, B, ldk, s * BK, tid);
        cp_commit();
    }

    for (int k = 0; k < NC; k++) {
        int rem = NC - 1 - k;
        if (rem >= 2)      { CP_WAIT(2); }
        else if (rem == 1) { CP_WAIT(1); }
        else               { CP_WAIT(0); }
        __syncthreads();
        if (k + 3 < NC) {
            load_stage(sm0 + (uint32_t)((k + 3) & (NSTG - 1)) * STAGE, A, B,
                       ldk, (k + 3) * BK, tid);
            cp_commit();
        }
        uint32_t sb = sm0 + (uint32_t)(k & (NSTG - 1)) * STAGE;
#pragma unroll
        for (int kk = 0; kk < 2; kk++) {
            const uint32_t kb = kk * 32;
            uint32_t ah[2][4], bh[4][4];
#pragma unroll
            for (int mt = 0; mt < 2; mt++)
                ldmx4(sb + ST_A + a_off + mt * 16 * ROWB + kb, ah[mt]);
#pragma unroll
            for (int p = 0; p < 4; p++)
                ldmx4(sb + ST_B + b_off + p * 16 * ROWB + kb, bh[p]);
#pragma unroll
            for (int p = 0; p < 4; p++)
#pragma unroll
                for (int q = 0; q < 2; q++)
#pragma unroll
                    for (int mt = 0; mt < 2; mt++)
                        mma16816(acc[mt][p * 2 + q], ah[mt], &bh[p][q * 2]);
        }
        __syncthreads();
    }
}

// ---------------- GEMM1: h = fp16(gelu(xg @ W1t^T + b1)) ----------------------
__global__ void __launch_bounds__(256, 2)
k_mma1(const float* __restrict__ b1) {
    int t = blockIdx.y;
    if (t >= g_ntiles) return;
    const int n0 = blockIdx.x * BN;
    const int base = g_tile_base[t], e = g_tile_expert[t], rows = g_tile_rows[t];

    extern __shared__ char dsm[];
    uint32_t sm0 = smem_u32(dsm);
    int tid = threadIdx.x;

    float acc[2][8][4];
    gemm_core(sm0, g_xg + (size_t)base * Dc,
              g_W1t + ((size_t)e * Fc + n0) * Dc, Dc, Dc / BK, tid, acc);

    const int lane = tid & 31, wid = tid >> 5;
    const int wm = (wid & 3) * 32, wn = (wid >> 2) * 64;
    const int rb = wm + (lane >> 2);
    const int cb = wn + (lane & 3) * 2;
    const float* b1e = b1 + (size_t)e * Fc + n0;
    float bv[8][2];
#pragma unroll
    for (int nt = 0; nt < 8; nt++) {
        bv[nt][0] = b1e[cb + nt * 8];
        bv[nt][1] = b1e[cb + nt * 8 + 1];
    }
#pragma unroll
    for (int mt = 0; mt < 2; mt++)
#pragma unroll
        for (int half = 0; half < 2; half++) {
            int r = rb + mt * 16 + half * 8;
            if (r >= rows) continue;
            size_t ro = (size_t)(base + r) * Fc + n0;
#pragma unroll
            for (int nt = 0; nt < 8; nt++) {
                float v0 = gelu_exact(acc[mt][nt][half * 2 + 0] + bv[nt][0]);
                float v1 = gelu_exact(acc[mt][nt][half * 2 + 1] + bv[nt][1]);
                *(uint32_t*)(g_h + ro + cb + nt * 8) =
                    pack2(__float2half_rn(v0), __float2half_rn(v1));
            }
        }
}

// ---------------- GEMM2: y[slot] = h @ W2t^T + b2 (plain stores) --------------
__global__ void __launch_bounds__(256, 2)
k_mma2(const float* __restrict__ b2) {
    int t = blockIdx.y;
    if (t >= g_ntiles) return;
    const int n0 = blockIdx.x * BN;
    const int base = g_tile_base[t], e = g_tile_expert[t], rows = g_tile_rows[t];

    extern __shared__ char dsm[];
    uint32_t sm0 = smem_u32(dsm);
    int tid = threadIdx.x;

    float acc[2][8][4];
    gemm_core(sm0, g_h + (size_t)base * Fc,
              g_W2t + ((size_t)e * Dc + n0) * Fc, Fc, Fc / BK, tid, acc);

    const int lane = tid & 31, wid = tid >> 5;
    const int wm = (wid & 3) * 32, wn = (wid >> 2) * 64;
    const int rb = wm + (lane >> 2);
    const int cb = wn + (lane & 3) * 2;
    const float* b2e = b2 + (size_t)e * Dc + n0;
    float bv[8][2];
#pragma unroll
    for (int nt = 0; nt < 8; nt++) {
        bv[nt][0] = b2e[cb + nt * 8];
        bv[nt][1] = b2e[cb + nt * 8 + 1];
    }
#pragma unroll
    for (int mt = 0; mt < 2; mt++)
#pragma unroll
        for (int half = 0; half < 2; half++) {
            int r = rb + mt * 16 + half * 8;
            if (r >= rows) continue;
            float* yrow = g_y + (size_t)(base + r) * Dc + n0;
#pragma unroll
            for (int nt = 0; nt < 8; nt++) {
                int c = cb + nt * 8;
                float2 v;
                v.x = acc[mt][nt][half * 2 + 0] + bv[nt][0];
                v.y = acc[mt][nt][half * 2 + 1] + bv[nt][1];
                *(float2*)(yrow + c) = v;
            }
        }
}

// ---------------- combine: out[t] = w0*y[s0] + w1*y[s1] -----------------------
__global__ void k_combine(float* __restrict__ out) {
    int t = blockIdx.x;
    int tid = threadIdx.x;
    int s0 = g_tok_slot[t * 2 + 0], s1 = g_tok_slot[t * 2 + 1];
    float w0 = g_tok_w[t * 2 + 0],  w1 = g_tok_w[t * 2 + 1];
    const float4* y0 = (const float4*)(g_y + (size_t)s0 * Dc);
    const float4* y1 = (const float4*)(g_y + (size_t)s1 * Dc);
    float4* o = (float4*)(out + (size_t)t * Dc);
    float4 a = y0[tid], b = y1[tid];
    float4 r;
    r.x = w0 * a.x + w1 * b.x;
    r.y = w0 * a.y + w1 * b.y;
    r.z = w0 * a.z + w1 * b.z;
    r.w = w0 * a.w + w1 * b.w;
    o[tid] = r;
}

// ---------------- launch (stream fork-join; capture-legal) ---------------------
extern "C" void kernel_launch(void* const* d_in, const int* in_sizes, int n_in,
                              void* d_out, int out_size) {
    const float* x  = (const float*)d_in[0];
    const float* Wg = (const float*)d_in[1];
    const float* bg = (const float*)d_in[2];
    const float* W1 = (const float*)d_in[3];
    const float* b1 = (const float*)d_in[4];
    const float* W2 = (const float*)d_in[5];
    const float* b2 = (const float*)d_in[6];
    float* out = (float*)d_out;

    static cudaStream_t s1 = nullptr, s2 = nullptr;
    static cudaEvent_t e_root = nullptr, e_w1 = nullptr, e_w2 = nullptr;
    static int configured = 0;
    if (!configured) {
        cudaFuncSetAttribute(k_mma1, cudaFuncAttributeMaxDynamicSharedMemorySize, SMEM_DYN);
        cudaFuncSetAttribute(k_mma2, cudaFuncAttributeMaxDynamicSharedMemorySize, SMEM_DYN);
        cudaStreamCreateWithFlags(&s1, cudaStreamNonBlocking);
        cudaStreamCreateWithFlags(&s2, cudaStreamNonBlocking);
        cudaEventCreateWithFlags(&e_root, cudaEventDisableTiming);
        cudaEventCreateWithFlags(&e_w1, cudaEventDisableTiming);
        cudaEventCreateWithFlags(&e_w2, cudaEventDisableTiming);
        configured = 1;
    }

    // fork: weight conversions on side streams
    cudaEventRecord(e_root, 0);
    cudaStreamWaitEvent(s1, e_root, 0);
    cudaStreamWaitEvent(s2, e_root, 0);
    k_tsplit<<<dim3(Fc / 32, Dc / 32, Ec), dim3(32, 8), 0, s1>>>(W1, 0, Dc, Fc);
    cudaEventRecord(e_w1, s1);
    k_tsplit<<<dim3(Dc / 32, Fc / 32, Ec), dim3(32, 8), 0, s2>>>(W2, 1, Fc, Dc);
    cudaEventRecord(e_w2, s2);

    // main stream: routing chain (overlaps W1/W2 conversion)
    k_init<<<1, 32>>>();
    k_gate<<<NTOK / 8, 256>>>(x, Wg, bg);
    k_setup<<<1, 1>>>();
    k_scatter<<<NTOK / 256, 256>>>();
    k_gather<<<NSLOT + PADR, 256>>>(x);

    // join W1 before GEMM1; W2 conversion keeps running under GEMM1
    cudaStreamWaitEvent(0, e_w1, 0);
    k_mma1<<<dim3(Fc / BN, MAX_TILES), 256, SMEM_DYN>>>(b1);

    // join W2 before GEMM2
    cudaStreamWaitEvent(0, e_w2, 0);
    k_mma2<<<dim3(Dc / BN, MAX_TILES), 256, SMEM_DYN>>>(b2);
    k_combine<<<NTOK, 256>>>(out);
}